// round 1
// baseline (speedup 1.0000x reference)
#include <cuda_runtime.h>
#include <cstdint>

#define N_ENT 100000
#define NB    50000
#define DD    128
#define RR    8
#define EE    200000

// Scratch: transformed embeddings for the current relation, and the global
// accumulator. Both ~51.2MB -> together they stay L2-resident (126MB L2).
__device__ float g_Y[(size_t)N_ENT * DD];
__device__ float g_agg[(size_t)N_ENT * DD];

// ---------------------------------------------------------------------------
// f32x2 packed helpers (Blackwell packed fp32 pipe: 2x FFMA throughput)
// ---------------------------------------------------------------------------
__device__ __forceinline__ unsigned long long dup_f32(float x) {
    unsigned long long r;
    unsigned int b = __float_as_uint(x);
    asm("mov.b64 %0, {%1, %1};" : "=l"(r) : "r"(b));
    return r;
}
__device__ __forceinline__ unsigned long long ffma2(unsigned long long a,
                                                    unsigned long long b,
                                                    unsigned long long c) {
    unsigned long long d;
    asm("fma.rn.f32x2 %0, %1, %2, %3;" : "=l"(d) : "l"(a), "l"(b), "l"(c));
    return d;
}
__device__ __forceinline__ float lo_f(unsigned long long p) {
    return __uint_as_float((unsigned int)(p & 0xffffffffull));
}
__device__ __forceinline__ float hi_f(unsigned long long p) {
    return __uint_as_float((unsigned int)(p >> 32));
}

// ---------------------------------------------------------------------------
// Zero the accumulator
// ---------------------------------------------------------------------------
__global__ void zero_kernel() {
    int n4 = N_ENT * DD / 4;
    for (int i = blockIdx.x * blockDim.x + threadIdx.x; i < n4;
         i += gridDim.x * blockDim.x)
        ((float4*)g_agg)[i] = make_float4(0.f, 0.f, 0.f, 0.f);
}

// ---------------------------------------------------------------------------
// GEMM: g_Y[n, o] = sum_k A[n, k] * W[k, o]    (A: nrows x 128, W: 128 x 128)
// Block: 256 threads, tile 256 rows x 128 cols. Thread: 16 rows x 8 cols,
// accumulated as 16x4 f32x2 pairs (cols paired; W pairs come free from
// LDS.128, the A scalar is duplicated into both halves).
// ---------------------------------------------------------------------------
#define TILE_R 256
#define GEMM_SMEM ((TILE_R * DD + DD * DD) * 4)   // 192 KB

__global__ void __launch_bounds__(256, 1)
gemm_y_kernel(const float* __restrict__ A, const float* __restrict__ W, int nrows)
{
    extern __shared__ float sm[];
    float* As = sm;                 // [TILE_R][128]
    float* Ws = sm + TILE_R * DD;   // [128][128]
    const int tid  = threadIdx.x;
    const int row0 = blockIdx.x * TILE_R;

    for (int i = tid; i < DD * DD / 4; i += 256)
        ((float4*)Ws)[i] = ((const float4*)W)[i];

    for (int i = tid; i < TILE_R * DD / 4; i += 256) {
        int row = i >> 5;  // 32 float4 per row
        float4 v;
        if (row0 + row < nrows)
            v = ((const float4*)A)[(size_t)(row0 + row) * (DD / 4) + (i & 31)];
        else
            v = make_float4(0.f, 0.f, 0.f, 0.f);
        ((float4*)As)[i] = v;
    }
    __syncthreads();

    const int tx = tid & 15;       // col group: cols tx*8 .. tx*8+7
    const int ty = tid >> 4;       // row group: rows ty*16 .. ty*16+15
    const float* asp = As + (ty * 16) * DD;
    const float* wsp = Ws + tx * 8;

    unsigned long long acc[16][4];
    #pragma unroll
    for (int i = 0; i < 16; i++) {
        #pragma unroll
        for (int j = 0; j < 4; j++) acc[i][j] = 0ull;
    }

    #pragma unroll 4
    for (int k = 0; k < DD; k++) {
        ulonglong2 w01 = *(const ulonglong2*)(wsp + (size_t)k * DD);
        ulonglong2 w23 = *(const ulonglong2*)(wsp + (size_t)k * DD + 4);
        #pragma unroll
        for (int i = 0; i < 16; i++) {
            unsigned long long a2 = dup_f32(asp[i * DD + k]);  // broadcast LDS
            acc[i][0] = ffma2(a2, w01.x, acc[i][0]);
            acc[i][1] = ffma2(a2, w01.y, acc[i][1]);
            acc[i][2] = ffma2(a2, w23.x, acc[i][2]);
            acc[i][3] = ffma2(a2, w23.y, acc[i][3]);
        }
    }

    #pragma unroll
    for (int i = 0; i < 16; i++) {
        int row = row0 + ty * 16 + i;
        if (row < nrows) {
            float* outp = g_Y + (size_t)row * DD + tx * 8;
            *(ulonglong2*)(outp)     = make_ulonglong2(acc[i][0], acc[i][1]);
            *(ulonglong2*)(outp + 4) = make_ulonglong2(acc[i][2], acc[i][3]);
        }
    }
}

// ---------------------------------------------------------------------------
// Scatter: agg[src, :] += val * Y[dst, :]   — one warp per edge, float4
// vector atomics (sm_90+) to quarter the REDG op count.
// ---------------------------------------------------------------------------
__global__ void scatter_kernel(const int* __restrict__ esrc,
                               const int* __restrict__ edst,
                               const float* __restrict__ eval)
{
    int e    = (blockIdx.x * blockDim.x + threadIdx.x) >> 5;
    int lane = threadIdx.x & 31;
    if (e >= EE) return;
    int   s = __ldg(esrc + e);
    int   d = __ldg(edst + e);
    float v = __ldg(eval + e);
    float4 y = *(const float4*)(g_Y + (size_t)d * DD + lane * 4);
    float4 c = make_float4(y.x * v, y.y * v, y.z * v, y.w * v);
    atomicAdd((float4*)(g_agg + (size_t)s * DD + lane * 4), c);
}

// ---------------------------------------------------------------------------
// Epilogue: out[b, :] = sigmoid( A[b, :] @ W_self + agg[idx[b], :] )
// Same GEMM structure, fused gather + sigmoid.
// ---------------------------------------------------------------------------
__global__ void __launch_bounds__(256, 1)
epilogue_kernel(const float* __restrict__ A, const float* __restrict__ W,
                const int* __restrict__ idx, float* __restrict__ out, int nrows)
{
    extern __shared__ float sm[];
    float* As = sm;
    float* Ws = sm + TILE_R * DD;
    const int tid  = threadIdx.x;
    const int row0 = blockIdx.x * TILE_R;

    for (int i = tid; i < DD * DD / 4; i += 256)
        ((float4*)Ws)[i] = ((const float4*)W)[i];
    for (int i = tid; i < TILE_R * DD / 4; i += 256) {
        int row = i >> 5;
        float4 v;
        if (row0 + row < nrows)
            v = ((const float4*)A)[(size_t)(row0 + row) * (DD / 4) + (i & 31)];
        else
            v = make_float4(0.f, 0.f, 0.f, 0.f);
        ((float4*)As)[i] = v;
    }
    __syncthreads();

    const int tx = tid & 15;
    const int ty = tid >> 4;
    const float* asp = As + (ty * 16) * DD;
    const float* wsp = Ws + tx * 8;

    unsigned long long acc[16][4];
    #pragma unroll
    for (int i = 0; i < 16; i++) {
        #pragma unroll
        for (int j = 0; j < 4; j++) acc[i][j] = 0ull;
    }

    #pragma unroll 4
    for (int k = 0; k < DD; k++) {
        ulonglong2 w01 = *(const ulonglong2*)(wsp + (size_t)k * DD);
        ulonglong2 w23 = *(const ulonglong2*)(wsp + (size_t)k * DD + 4);
        #pragma unroll
        for (int i = 0; i < 16; i++) {
            unsigned long long a2 = dup_f32(asp[i * DD + k]);
            acc[i][0] = ffma2(a2, w01.x, acc[i][0]);
            acc[i][1] = ffma2(a2, w01.y, acc[i][1]);
            acc[i][2] = ffma2(a2, w23.x, acc[i][2]);
            acc[i][3] = ffma2(a2, w23.y, acc[i][3]);
        }
    }

    #pragma unroll
    for (int i = 0; i < 16; i++) {
        int row = row0 + ty * 16 + i;
        if (row < nrows) {
            int g = __ldg(idx + row);
            const float* ap = g_agg + (size_t)g * DD + tx * 8;
            float4 b0 = *(const float4*)ap;
            float4 b1 = *(const float4*)(ap + 4);
            float x0 = lo_f(acc[i][0]) + b0.x;
            float x1 = hi_f(acc[i][0]) + b0.y;
            float x2 = lo_f(acc[i][1]) + b0.z;
            float x3 = hi_f(acc[i][1]) + b0.w;
            float x4 = lo_f(acc[i][2]) + b1.x;
            float x5 = hi_f(acc[i][2]) + b1.y;
            float x6 = lo_f(acc[i][3]) + b1.z;
            float x7 = hi_f(acc[i][3]) + b1.w;
            float4 o0 = make_float4(1.f / (1.f + __expf(-x0)),
                                    1.f / (1.f + __expf(-x1)),
                                    1.f / (1.f + __expf(-x2)),
                                    1.f / (1.f + __expf(-x3)));
            float4 o1 = make_float4(1.f / (1.f + __expf(-x4)),
                                    1.f / (1.f + __expf(-x5)),
                                    1.f / (1.f + __expf(-x6)),
                                    1.f / (1.f + __expf(-x7)));
            float* op = out + (size_t)row * DD + tx * 8;
            *(float4*)op       = o0;
            *(float4*)(op + 4) = o1;
        }
    }
}

// ---------------------------------------------------------------------------
extern "C" void kernel_launch(void* const* d_in, const int* in_sizes, int n_in,
                              void* d_out, int out_size)
{
    const float* emb      = (const float*)d_in[0];
    const float* head_e   = (const float*)d_in[1];
    const float* tail_e   = (const float*)d_in[2];
    const float* relk     = (const float*)d_in[3];
    const float* selfk    = (const float*)d_in[4];
    const float* edge_val = (const float*)d_in[5];
    const int*   head_idx = (const int*)d_in[6];
    const int*   tail_idx = (const int*)d_in[7];
    const int*   edge_src = (const int*)d_in[8];
    const int*   edge_dst = (const int*)d_in[9];
    float*       out      = (float*)d_out;

    cudaFuncSetAttribute(gemm_y_kernel,
                         cudaFuncAttributeMaxDynamicSharedMemorySize, GEMM_SMEM);
    cudaFuncSetAttribute(epilogue_kernel,
                         cudaFuncAttributeMaxDynamicSharedMemorySize, GEMM_SMEM);

    zero_kernel<<<2048, 256>>>();

    const int gemm_blocks = (N_ENT + TILE_R - 1) / TILE_R;      // 391
    const int scat_blocks = (EE + 7) / 8;                       // 25000 (8 warps/blk)
    for (int r = 0; r < RR; r++) {
        gemm_y_kernel<<<gemm_blocks, 256, GEMM_SMEM>>>(
            emb, relk + (size_t)r * DD * DD, N_ENT);
        scatter_kernel<<<scat_blocks, 256>>>(
            edge_src + (size_t)r * EE, edge_dst + (size_t)r * EE,
            edge_val + (size_t)r * EE);
    }

    const int epi_blocks = (NB + TILE_R - 1) / TILE_R;          // 196
    epilogue_kernel<<<epi_blocks, 256, GEMM_SMEM>>>(
        head_e, selfk, head_idx, out, NB);
    epilogue_kernel<<<epi_blocks, 256, GEMM_SMEM>>>(
        tail_e, selfk, tail_idx, out + (size_t)NB * DD, NB);
}